// round 15
// baseline (speedup 1.0000x reference)
#include <cuda_runtime.h>
#include <cuda_bf16.h>
#include <math.h>

#define NN   4096
#define FF   256
#define ELLW 256
#define TBITS 19
#define TSIZE (1 << TBITS)
#define TMASK (TSIZE - 1)

// ---------------- scratch (device globals) ----------------
__device__ int   g_hkey[TSIZE];
__device__ float g_hvalF[TSIZE];
__device__ float g_hvalR[TSIZE];
__device__ float g_deg[NN];
__device__ float g_dinv[NN];
__device__ int   g_cnt[NN];
__device__ int4  g_ell[NN * ELLW];   // AoS: {col, lre_bits, lim_bits, pad}

// weight-side constants
__device__ float g_K[6][256 * 64];    // K0re,K0im,K1re,K1im,K2re,K2im (padded to 64)
__device__ float g_Cm[10][256 * 64];  // C0re,C0im,...,C4re,C4im
__device__ float g_cvec[64];
__device__ float g_w0re[64], g_w1re[64], g_w1im[64], g_w2re[64], g_w2im[64];
__device__ float g_l1re[NN], g_l1im[NN], g_l2re[NN], g_l2im[NN];

// activations (all 4096x64)
__device__ float g_Y[10][NN * 64];    // Y0re,Y0im,...,Y4re,Y4im
__device__ float g_TAre[NN * 64], g_TAim[NN * 64];
__device__ float g_TBre[NN * 64], g_TBim[NN * 64];
__device__ float g_PIm[NN * 64];

__device__ __forceinline__ unsigned hash_key(int key) {
    return ((unsigned)key * 2654435761u) >> (32 - TBITS);
}

// ---------------- graph build (proven) ----------------
__global__ void zero_kernel() {
    int idx = blockIdx.x * blockDim.x + threadIdx.x;
    if (idx < TSIZE) { g_hkey[idx] = -1; g_hvalF[idx] = 0.f; g_hvalR[idx] = 0.f; }
    if (idx < NN)    { g_deg[idx] = 0.f; g_cnt[idx] = 0; }
}

__global__ void insert_kernel(const int* __restrict__ edges,
                              const float* __restrict__ w, int E) {
    int e = blockIdx.x * blockDim.x + threadIdx.x;
    if (e >= E) return;
    int r = edges[e];
    int c = edges[E + e];
    float we = w[e];
    atomicAdd(&g_deg[r], 0.5f * we);
    atomicAdd(&g_deg[c], 0.5f * we);
    int lo = min(r, c), hi = max(r, c);
    int key = (lo << 12) | hi;
    unsigned h = hash_key(key) & TMASK;
    while (true) {
        int prev = atomicCAS(&g_hkey[h], -1, key);
        if (prev == -1 || prev == key) {
            if (r <= c) atomicAdd(&g_hvalF[h], we);
            else        atomicAdd(&g_hvalR[h], we);
            break;
        }
        h = (h + 1) & TMASK;
    }
}

__global__ void dinv_kernel() {
    int i = blockIdx.x * blockDim.x + threadIdx.x;
    if (i < NN) {
        float d = g_deg[i];
        if (d == 0.f) d = 1.f;
        g_dinv[i] = rsqrtf(d);
    }
}

__device__ __forceinline__ void ell_push(int r, int c, float lre, float lim) {
    int slot = atomicAdd(&g_cnt[r], 1);
    if (slot < ELLW) {
        g_ell[r * ELLW + slot] =
            make_int4(c, __float_as_int(lre), __float_as_int(lim), 0);
    }
}

__global__ void emit_kernel(const float* __restrict__ qp) {
    int s = blockIdx.x * blockDim.x + threadIdx.x;
    if (s >= TSIZE) return;
    int key = g_hkey[s];
    if (key < 0) return;
    int i = key >> 12;
    int j = key & 4095;
    float F = g_hvalF[s];
    float R = g_hvalR[s];
    float q = __ldg(qp);
    if (i == j) {
        float di = g_dinv[i];
        ell_push(i, i, -di * di * F, 0.f);
        return;
    }
    float asym = 0.5f * (F + R);
    float an = g_dinv[i] * asym * g_dinv[j];
    float th = 6.283185307179586f * q * (F - R);
    float sn, cs;
    __sincosf(th, &sn, &cs);
    ell_push(i, j, -an * cs,  an * sn);
    ell_push(j, i, -an * cs, -an * sn);
}

// ---------------- K matrices: g_K[m] = (s0*W20 + s1*W21 + s2*W22) @ Wc_part^T ----------------
// m: 0 K0re(part i, 1,0,-1) 1 K0im(part r) 2 K1re(0,1,0) 3 K1im 4 K2re(0,0,2) 5 K2im
__global__ void cmat_kernel(const float* __restrict__ W, const float* __restrict__ Wc) {
    __shared__ float wc[40 * 257];
    int mat = blockIdx.y;     // 0..5
    int strip = blockIdx.x;   // 0..7
    int tid = threadIdx.x;
    int part = (mat & 1) ? 0 : 1;   // even mats = re -> Wci (part 1); odd = im -> Wcr (part 0)
    float s0 = 0.f, s1 = 0.f, s2 = 0.f;
    switch (mat >> 1) {
        case 0: s0 = 1.f; s2 = -1.f; break;
        case 1: s1 = 1.f; break;
        default: s2 = 2.f; break;
    }
    for (int idx = tid; idx < 40 * 256; idx += 256) {
        int c = idx >> 8, f = idx & 255;
        wc[c * 257 + f] = Wc[c * 512 + part * 256 + f];
    }
    __syncthreads();
    int a = strip * 32 + (tid >> 3);
    int cg = tid & 7;
    float acc[5] = {0.f, 0.f, 0.f, 0.f, 0.f};
    for (int f = 0; f < 256; f++) {
        float w = 0.f;
        if (s0 != 0.f) w += s0 * W[a * 256 + f];
        if (s1 != 0.f) w += s1 * W[65536 + a * 256 + f];
        if (s2 != 0.f) w += s2 * W[131072 + a * 256 + f];
        #pragma unroll
        for (int j = 0; j < 5; j++)
            acc[j] = fmaf(w, wc[(cg * 5 + j) * 257 + f], acc[j]);
    }
    #pragma unroll
    for (int j = 0; j < 5; j++)
        g_K[mat][a * 64 + cg * 5 + j] = acc[j];
    for (int idx = tid; idx < 32 * 24; idx += 256) {
        int r = idx / 24, c = 40 + idx % 24;
        g_K[mat][(strip * 32 + r) * 64 + c] = 0.f;
    }
}

// ---------------- C matrices: Cp = sum_{(j,k) in terms(p)} Ej @ Kk ----------------
// E0 = W10 - W12, E1 = W11, E2 = 2*W12  (from W1)
__global__ void cmatC_kernel(const float* __restrict__ W1) {
    const int nterm[5] = {1, 2, 3, 2, 1};
    const int tj[5][3] = {{0,-1,-1},{1,0,-1},{2,1,0},{2,1,-1},{2,-1,-1}};
    const int tk[5][3] = {{0,-1,-1},{0,1,-1},{0,1,2},{1,2,-1},{2,-1,-1}};
    int m = blockIdx.y;       // 0..9
    int strip = blockIdx.x;   // 0..7
    int p = m >> 1, part = m & 1;
    int tid = threadIdx.x;
    int a = strip * 32 + (tid >> 3);
    int cg = tid & 7;
    float acc[8] = {0.f, 0.f, 0.f, 0.f, 0.f, 0.f, 0.f, 0.f};
    for (int t = 0; t < nterm[p]; t++) {
        int j = tj[p][t], k = tk[p][t];
        const float* Kp = g_K[2 * k + part];
        float c0 = (j == 0) ? 1.f : 0.f;
        float c1 = (j == 1) ? 1.f : 0.f;
        float c2 = (j == 0) ? -1.f : ((j == 2) ? 2.f : 0.f);
        for (int f = 0; f < 256; f++) {
            float e = 0.f;
            if (c0 != 0.f) e += c0 * W1[a * 256 + f];
            if (c1 != 0.f) e += c1 * W1[65536 + a * 256 + f];
            if (c2 != 0.f) e += c2 * W1[131072 + a * 256 + f];
            #pragma unroll
            for (int x = 0; x < 8; x++)
                acc[x] = fmaf(e, Kp[f * 64 + cg * 8 + x], acc[x]);
        }
    }
    #pragma unroll
    for (int x = 0; x < 8; x++)
        g_Cm[m][a * 64 + cg * 8 + x] = acc[x];
}

// ---------------- bias vectors ----------------
__global__ void cvec_kernel(const float* __restrict__ b2, const float* __restrict__ Wc) {
    int c = threadIdx.x;
    if (c >= 64) return;
    float s = 0.f;
    if (c < 40)
        for (int f = 0; f < 256; f++)
            s += b2[f] * (Wc[c * 512 + f] + Wc[c * 512 + 256 + f]);
    g_cvec[c] = s;
}

__global__ void uw_kernel(const float* __restrict__ b1) {
    int j = threadIdx.x;
    if (j >= 64) return;
    float ur[3], ui[3];
    #pragma unroll
    for (int k = 0; k < 3; k++) {
        float sre = 0.f, sim = 0.f;
        for (int f = 0; f < 256; f++) {
            float b = b1[f];
            sre = fmaf(b, g_K[2 * k][f * 64 + j], sre);
            sim = fmaf(b, g_K[2 * k + 1][f * 64 + j], sim);
        }
        ur[k] = sre; ui[k] = sim;
    }
    g_w0re[j] = ur[0] - ui[0];
    g_w1re[j] = ur[1] - ui[1];  g_w1im[j] = ur[1] + ui[1];
    g_w2re[j] = ur[2] - ui[2];  g_w2im[j] = ur[2] + ui[2];
}

// ---------------- l vectors: l1 = L @ 1 ; l2 = L @ l1 ----------------
__global__ void lvec1_kernel() {
    int warp = threadIdx.x >> 5, lane = threadIdx.x & 31;
    int row = blockIdx.x * 8 + warp;
    int cnt = g_cnt[row];
    if (cnt > ELLW) cnt = ELLW;
    float sre = 0.f, sim = 0.f;
    for (int k = lane; k < cnt; k += 32) {
        int4 v = g_ell[row * ELLW + k];
        sre += __int_as_float(v.y);
        sim += __int_as_float(v.z);
    }
    #pragma unroll
    for (int o = 16; o > 0; o >>= 1) {
        sre += __shfl_xor_sync(0xffffffffu, sre, o);
        sim += __shfl_xor_sync(0xffffffffu, sim, o);
    }
    if (lane == 0) { g_l1re[row] = sre; g_l1im[row] = sim; }
}

__global__ void lvec2_kernel() {
    int warp = threadIdx.x >> 5, lane = threadIdx.x & 31;
    int row = blockIdx.x * 8 + warp;
    int cnt = g_cnt[row];
    if (cnt > ELLW) cnt = ELLW;
    float sre = 0.f, sim = 0.f;
    for (int k = lane; k < cnt; k += 32) {
        int4 v = g_ell[row * ELLW + k];
        float lr = __int_as_float(v.y);
        float li = __int_as_float(v.z);
        float xr = g_l1re[v.x], xi = g_l1im[v.x];
        sre += lr * xr - li * xi;
        sim += lr * xi + li * xr;
    }
    #pragma unroll
    for (int o = 16; o > 0; o >>= 1) {
        sre += __shfl_xor_sync(0xffffffffu, sre, o);
        sim += __shfl_xor_sync(0xffffffffu, sim, o);
    }
    if (lane == 0) { g_l2re[row] = sre; g_l2im[row] = sim; }
}

// ---------------- GEMM machinery (proven) ----------------
__device__ __forceinline__ unsigned pack_bf2(float x, float y) {
    __nv_bfloat162 t;
    t.x = __float2bfloat16_rn(x);
    t.y = __float2bfloat16_rn(y);
    return *reinterpret_cast<unsigned*>(&t);
}

#define MMA_BF16(d, a, b)                                                        \
    asm volatile("mma.sync.aligned.m16n8k16.row.col.f32.bf16.bf16.f32 "          \
                 "{%0,%1,%2,%3},{%4,%5,%6,%7},{%8,%9},{%0,%1,%2,%3};"            \
                 : "+f"(d[0]), "+f"(d[1]), "+f"(d[2]), "+f"(d[3])                 \
                 : "r"(a[0]), "r"(a[1]), "r"(a[2]), "r"(a[3]), "r"(b[0]), "r"(b[1]))

#define LDSM_X4(r, addr)                                                         \
    asm volatile("ldmatrix.sync.aligned.m8n8.x4.shared.b16 {%0,%1,%2,%3}, [%4];" \
                 : "=r"(r[0]), "=r"(r[1]), "=r"(r[2]), "=r"(r[3]) : "r"(addr) : "memory")

#define LDSM_X4_T(r, addr)                                                             \
    asm volatile("ldmatrix.sync.aligned.m8n8.x4.trans.shared.b16 {%0,%1,%2,%3}, [%4];" \
                 : "=r"(r[0]), "=r"(r[1]), "=r"(r[2]), "=r"(r[3]) : "r"(addr) : "memory")

#define AST 20
#define WST 36

// ---------- dual plane products with sign on 2nd term: O[p] = Xr@C0[p] + sg[p]*(Xi@C1[p]) ----------
struct PPArgs {
    const float* Xr;
    const float* Xi;
    const float* C0[10];
    const float* C1[10];
    float sg[10];
    float* O[10];
};

__global__ void __launch_bounds__(256, 2)
ppY_kernel(PPArgs pp) {
    __shared__ unsigned ash[128 * AST], asl[128 * AST];
    __shared__ unsigned wsh[32 * WST],  wsl[32 * WST];

    int tid = threadIdx.x;
    int lane = tid & 31;
    int warp = tid >> 5;
    int wm = warp >> 2;
    int wn = warp & 3;
    int p = blockIdx.x;
    int m0 = blockIdx.y * 128;
    float* Op = pp.O[p];
    float sg = pp.sg[p];

    float acc[4][2][4];
    #pragma unroll
    for (int mt = 0; mt < 4; mt++)
        #pragma unroll
        for (int nt = 0; nt < 2; nt++)
            #pragma unroll
            for (int r = 0; r < 4; r++) acc[mt][nt][r] = 0.f;

    unsigned a_hi_base = (unsigned)__cvta_generic_to_shared(ash);
    unsigned a_lo_base = (unsigned)__cvta_generic_to_shared(asl);
    unsigned w_hi_base = (unsigned)__cvta_generic_to_shared(wsh);
    unsigned w_lo_base = (unsigned)__cvta_generic_to_shared(wsl);

    unsigned a_off = ((wm * 64 + (lane & 15)) * (AST * 2) + (lane >> 4) * 8) * 2;
    unsigned w_off = (((((lane >> 3) & 1) * 8 + (lane & 7)) * (WST * 2)) + wn * 16 + (lane >> 4) * 8) * 2;

    for (int ks = 0; ks < 16; ks++) {
        int plane = ks >> 3;
        int kc = (ks & 7) * 32;
        const float* Ap = plane ? pp.Xi : pp.Xr;
        const float* Cm = plane ? pp.C1[p] : pp.C0[p];
        float s = plane ? sg : 1.f;
        #pragma unroll
        for (int t = 0; t < 4; t++) {
            int idx = tid + t * 256;
            int r = idx >> 3;
            int c4 = (idx & 7) * 4;
            float4 v = *reinterpret_cast<const float4*>(&Ap[(m0 + r) * 256 + kc + c4]);
            float hx = __bfloat162float(__float2bfloat16_rn(v.x));
            float hy = __bfloat162float(__float2bfloat16_rn(v.y));
            float hz = __bfloat162float(__float2bfloat16_rn(v.z));
            float hw = __bfloat162float(__float2bfloat16_rn(v.w));
            int o = r * AST + (c4 >> 1);
            ash[o]     = pack_bf2(v.x, v.y);
            ash[o + 1] = pack_bf2(v.z, v.w);
            asl[o]     = pack_bf2(v.x - hx, v.y - hy);
            asl[o + 1] = pack_bf2(v.z - hz, v.w - hw);
        }
        #pragma unroll
        for (int t = 0; t < 2; t++) {
            int idx = tid + t * 256;
            int kk = idx >> 4;
            int n4 = (idx & 15) * 4;
            float4 v = *reinterpret_cast<const float4*>(&Cm[(kc + kk) * 64 + n4]);
            v.x *= s; v.y *= s; v.z *= s; v.w *= s;
            float hx = __bfloat162float(__float2bfloat16_rn(v.x));
            float hy = __bfloat162float(__float2bfloat16_rn(v.y));
            float hz = __bfloat162float(__float2bfloat16_rn(v.z));
            float hw = __bfloat162float(__float2bfloat16_rn(v.w));
            int o = kk * WST + (n4 >> 1);
            wsh[o]     = pack_bf2(v.x, v.y);
            wsh[o + 1] = pack_bf2(v.z, v.w);
            wsl[o]     = pack_bf2(v.x - hx, v.y - hy);
            wsl[o + 1] = pack_bf2(v.z - hz, v.w - hw);
        }
        __syncthreads();

        #pragma unroll
        for (int h = 0; h < 32; h += 16) {
            unsigned ah[4][4], al[4][4];
            #pragma unroll
            for (int mt = 0; mt < 4; mt++) {
                unsigned off = a_off + (mt * 16 * AST * 2 + h) * 2;
                LDSM_X4(ah[mt], a_hi_base + off);
                LDSM_X4(al[mt], a_lo_base + off);
            }
            unsigned bh4[4], bl4[4];
            {
                unsigned off = w_off + (h * WST * 2) * 2;
                LDSM_X4_T(bh4, w_hi_base + off);
                LDSM_X4_T(bl4, w_lo_base + off);
            }
            #pragma unroll
            for (int mt = 0; mt < 4; mt++) {
                #pragma unroll
                for (int nt = 0; nt < 2; nt++) {
                    unsigned bh[2] = {bh4[nt * 2], bh4[nt * 2 + 1]};
                    unsigned bl[2] = {bl4[nt * 2], bl4[nt * 2 + 1]};
                    MMA_BF16(acc[mt][nt], ah[mt], bh);
                    MMA_BF16(acc[mt][nt], ah[mt], bl);
                    MMA_BF16(acc[mt][nt], al[mt], bh);
                }
            }
        }
        __syncthreads();
    }

    int g = lane >> 2, tig = lane & 3;
    #pragma unroll
    for (int mt = 0; mt < 4; mt++) {
        #pragma unroll
        for (int nt = 0; nt < 2; nt++) {
            int n = wn * 16 + nt * 8 + tig * 2;
            int ml0 = m0 + wm * 64 + mt * 16 + g;
            float* c0 = acc[mt][nt];
            *reinterpret_cast<float2*>(&Op[ml0 * 64 + n])       = make_float2(c0[0], c0[1]);
            *reinterpret_cast<float2*>(&Op[(ml0 + 8) * 64 + n]) = make_float2(c0[2], c0[3]);
        }
    }
}

// ---------------- Horner narrow spmm: Tout = Yadd + L * Tin (complex) ----------------
__global__ void hornerC_kernel(const float* __restrict__ Yre, const float* __restrict__ Yim,
                               const float* __restrict__ Tinre, const float* __restrict__ Tinim,
                               float* __restrict__ Tore, float* __restrict__ Toim) {
    int row = blockIdx.x;
    int t = threadIdx.x;   // 64
    int cnt = g_cnt[row];
    if (cnt > ELLW) cnt = ELLW;
    __shared__ int   sc[ELLW];
    __shared__ float slr[ELLW];
    __shared__ float sli[ELLW];
    for (int k = t; k < cnt; k += 64) {
        int4 v = g_ell[row * ELLW + k];
        sc [k] = v.x;
        slr[k] = __int_as_float(v.y);
        sli[k] = __int_as_float(v.z);
    }
    __syncthreads();
    float vr = 0.f, vi = 0.f;
    #pragma unroll 4
    for (int k = 0; k < cnt; k++) {
        int c = sc[k];
        float lr = slr[k];
        float li = sli[k];
        float tr = __ldg(&Tinre[c * 64 + t]);
        float ti = __ldg(&Tinim[c * 64 + t]);
        vr = fmaf(lr, tr, vr); vr = fmaf(-li, ti, vr);
        vi = fmaf(lr, ti, vi); vi = fmaf(li, tr, vi);
    }
    int o = row * 64 + t;
    Tore[o] = Yre[o] + vr;
    Toim[o] = Yim[o] + vi;
}

// imag-only final pass: PIm = Y0im + Im(L * Tin)
__global__ void hornerI_kernel(const float* __restrict__ Y0im,
                               const float* __restrict__ Tinre, const float* __restrict__ Tinim,
                               float* __restrict__ PIm) {
    int row = blockIdx.x;
    int t = threadIdx.x;   // 64
    int cnt = g_cnt[row];
    if (cnt > ELLW) cnt = ELLW;
    __shared__ int   sc[ELLW];
    __shared__ float slr[ELLW];
    __shared__ float sli[ELLW];
    for (int k = t; k < cnt; k += 64) {
        int4 v = g_ell[row * ELLW + k];
        sc [k] = v.x;
        slr[k] = __int_as_float(v.y);
        sli[k] = __int_as_float(v.z);
    }
    __syncthreads();
    float vi = 0.f;
    #pragma unroll 4
    for (int k = 0; k < cnt; k++) {
        int c = sc[k];
        vi = fmaf(slr[k], __ldg(&Tinim[c * 64 + t]), vi);
        vi = fmaf(sli[k], __ldg(&Tinre[c * 64 + t]), vi);
    }
    int o = row * 64 + t;
    PIm[o] = Y0im[o] + vi;
}

// ---------------- final: logits = -PIm + rank1 + cvec + bc -> log_softmax ----------------
__global__ void final_kernel(const float* __restrict__ bc, float* __restrict__ out) {
    int warp = threadIdx.x >> 5, lane = threadIdx.x & 31;
    int row = blockIdx.x * 8 + warp;
    float l1r = g_l1re[row], l1i = g_l1im[row];
    float l2r = g_l2re[row], l2i = g_l2im[row];
    float a = -3.4e38f, b = -3.4e38f;
    if (lane < 40) {
        int o = row * 64 + lane;
        a = -g_PIm[o] + g_w0re[lane]
          + l1r * g_w1re[lane] - l1i * g_w1im[lane]
          + l2r * g_w2re[lane] - l2i * g_w2im[lane]
          + g_cvec[lane] + bc[lane];
    }
    if (lane + 32 < 40) {
        int o = row * 64 + lane + 32;
        b = -g_PIm[o] + g_w0re[lane + 32]
          + l1r * g_w1re[lane + 32] - l1i * g_w1im[lane + 32]
          + l2r * g_w2re[lane + 32] - l2i * g_w2im[lane + 32]
          + g_cvec[lane + 32] + bc[lane + 32];
    }
    float m = fmaxf(a, b);
    #pragma unroll
    for (int o = 16; o > 0; o >>= 1) m = fmaxf(m, __shfl_xor_sync(0xffffffffu, m, o));
    float s = ((lane < 40) ? expf(a - m) : 0.f) + ((lane + 32 < 40) ? expf(b - m) : 0.f);
    #pragma unroll
    for (int o = 16; o > 0; o >>= 1) s += __shfl_xor_sync(0xffffffffu, s, o);
    float lse = m + logf(s);
    if (lane < 40)      out[row * 40 + lane]      = a - lse;
    if (lane + 32 < 40) out[row * 40 + lane + 32] = b - lse;
}

// ---------------- launch ----------------
extern "C" void kernel_launch(void* const* d_in, const int* in_sizes, int n_in,
                              void* d_out, int out_size) {
    const float* real = (const float*)d_in[0];
    const float* imag = (const float*)d_in[1];
    const int*   edges = (const int*)d_in[2];
    const float* qp = (const float*)d_in[3];
    const float* ew = (const float*)d_in[4];
    const float* W1 = (const float*)d_in[5];
    const float* b1 = (const float*)d_in[6];
    const float* W2 = (const float*)d_in[7];
    const float* b2 = (const float*)d_in[8];
    const float* Wc = (const float*)d_in[9];
    const float* bc = (const float*)d_in[10];
    float* out = (float*)d_out;
    int E = in_sizes[4];

    float *Cbase, *Ybase, *TAre, *TAim, *TBre, *TBim, *PIm;
    cudaGetSymbolAddress((void**)&Cbase, g_Cm);
    cudaGetSymbolAddress((void**)&Ybase, g_Y);
    cudaGetSymbolAddress((void**)&TAre, g_TAre);
    cudaGetSymbolAddress((void**)&TAim, g_TAim);
    cudaGetSymbolAddress((void**)&TBre, g_TBre);
    cudaGetSymbolAddress((void**)&TBim, g_TBim);
    cudaGetSymbolAddress((void**)&PIm,  g_PIm);

    // graph build
    zero_kernel<<<TSIZE / 256, 256>>>();
    insert_kernel<<<(E + 255) / 256, 256>>>(edges, ew, E);
    dinv_kernel<<<NN / 256, 256>>>();
    emit_kernel<<<TSIZE / 256, 256>>>(qp);

    // weight-side constants
    cmat_kernel<<<dim3(8, 6), 256>>>(W2, Wc);
    cvec_kernel<<<1, 64>>>(b2, Wc);
    cmatC_kernel<<<dim3(8, 10), 256>>>(W1);
    uw_kernel<<<1, 64>>>(b1);
    lvec1_kernel<<<NN / 8, 256>>>();
    lvec2_kernel<<<NN / 8, 256>>>();

    // Y_p = Xc @ C_p  (complex), 10 real outputs
    PPArgs pp;
    pp.Xr = real;
    pp.Xi = imag;
    for (int p = 0; p < 5; p++) {
        pp.C0[2 * p]     = Cbase + (2 * p) * 16384;       // Cp_re
        pp.C1[2 * p]     = Cbase + (2 * p + 1) * 16384;   // Cp_im
        pp.sg[2 * p]     = -1.f;                          // Yre = Xr Cre - Xi Cim
        pp.O [2 * p]     = Ybase + (2 * p) * (NN * 64);
        pp.C0[2 * p + 1] = Cbase + (2 * p + 1) * 16384;
        pp.C1[2 * p + 1] = Cbase + (2 * p) * 16384;
        pp.sg[2 * p + 1] = 1.f;                           // Yim = Xr Cim + Xi Cre
        pp.O [2 * p + 1] = Ybase + (2 * p + 1) * (NN * 64);
    }
    ppY_kernel<<<dim3(10, 32), 256>>>(pp);

    // Horner: P = Y0 + L(Y1 + L(Y2 + L(Y3 + L Y4)))
    #define YRE(p) (Ybase + (2 * (p)) * (NN * 64))
    #define YIM(p) (Ybase + (2 * (p) + 1) * (NN * 64))
    hornerC_kernel<<<NN, 64>>>(YRE(3), YIM(3), YRE(4), YIM(4), TAre, TAim);
    hornerC_kernel<<<NN, 64>>>(YRE(2), YIM(2), TAre, TAim, TBre, TBim);
    hornerC_kernel<<<NN, 64>>>(YRE(1), YIM(1), TBre, TBim, TAre, TAim);
    hornerI_kernel<<<NN, 64>>>(YIM(0), TAre, TAim, PIm);
    #undef YRE
    #undef YIM

    final_kernel<<<NN / 8, 256>>>(bc, out);
}

// round 16
// speedup vs baseline: 1.5313x; 1.5313x over previous
#include <cuda_runtime.h>
#include <cuda_bf16.h>
#include <math.h>

#define NN   4096
#define FF   256
#define ELLW 256
#define TBITS 19
#define TSIZE (1 << TBITS)
#define TMASK (TSIZE - 1)

// ---------------- scratch (device globals) ----------------
__device__ int   g_hkey[TSIZE];
__device__ float g_hvalF[TSIZE];
__device__ float g_hvalR[TSIZE];
__device__ float g_deg[NN];
__device__ float g_dinv[NN];
__device__ int   g_cnt[NN];
__device__ int4  g_ell[NN * ELLW];   // AoS: {col, lre_bits, lim_bits, pad}

// weight-side constants
__device__ float g_K[6][256 * 64];    // K0re,K0im,K1re,K1im,K2re,K2im (padded to 64)
__device__ float g_Cm[10][256 * 64];  // C0re,C0im,...,C4re,C4im
__device__ float g_cvec[64];
__device__ float g_w0re[64], g_w1re[64], g_w1im[64], g_w2re[64], g_w2im[64];
__device__ float g_l1re[NN], g_l1im[NN], g_l2re[NN], g_l2im[NN];

// activations (all 4096x64)
__device__ float g_Y[10][NN * 64];    // Y0re,Y0im,...,Y4re,Y4im
__device__ float g_TAre[NN * 64], g_TAim[NN * 64];
__device__ float g_TBre[NN * 64], g_TBim[NN * 64];
__device__ float g_PIm[NN * 64];

__device__ __forceinline__ unsigned hash_key(int key) {
    return ((unsigned)key * 2654435761u) >> (32 - TBITS);
}

// ---------------- graph build (proven) ----------------
__global__ void zero_kernel() {
    int idx = blockIdx.x * blockDim.x + threadIdx.x;
    if (idx < TSIZE) { g_hkey[idx] = -1; g_hvalF[idx] = 0.f; g_hvalR[idx] = 0.f; }
    if (idx < NN)    { g_deg[idx] = 0.f; g_cnt[idx] = 0; }
}

__global__ void insert_kernel(const int* __restrict__ edges,
                              const float* __restrict__ w, int E) {
    int e = blockIdx.x * blockDim.x + threadIdx.x;
    if (e >= E) return;
    int r = edges[e];
    int c = edges[E + e];
    float we = w[e];
    atomicAdd(&g_deg[r], 0.5f * we);
    atomicAdd(&g_deg[c], 0.5f * we);
    int lo = min(r, c), hi = max(r, c);
    int key = (lo << 12) | hi;
    unsigned h = hash_key(key) & TMASK;
    while (true) {
        int prev = atomicCAS(&g_hkey[h], -1, key);
        if (prev == -1 || prev == key) {
            if (r <= c) atomicAdd(&g_hvalF[h], we);
            else        atomicAdd(&g_hvalR[h], we);
            break;
        }
        h = (h + 1) & TMASK;
    }
}

__global__ void dinv_kernel() {
    int i = blockIdx.x * blockDim.x + threadIdx.x;
    if (i < NN) {
        float d = g_deg[i];
        if (d == 0.f) d = 1.f;
        g_dinv[i] = rsqrtf(d);
    }
}

__device__ __forceinline__ void ell_push(int r, int c, float lre, float lim) {
    int slot = atomicAdd(&g_cnt[r], 1);
    if (slot < ELLW) {
        g_ell[r * ELLW + slot] =
            make_int4(c, __float_as_int(lre), __float_as_int(lim), 0);
    }
}

__global__ void emit_kernel(const float* __restrict__ qp) {
    int s = blockIdx.x * blockDim.x + threadIdx.x;
    if (s >= TSIZE) return;
    int key = g_hkey[s];
    if (key < 0) return;
    int i = key >> 12;
    int j = key & 4095;
    float F = g_hvalF[s];
    float R = g_hvalR[s];
    float q = __ldg(qp);
    if (i == j) {
        float di = g_dinv[i];
        ell_push(i, i, -di * di * F, 0.f);
        return;
    }
    float asym = 0.5f * (F + R);
    float an = g_dinv[i] * asym * g_dinv[j];
    float th = 6.283185307179586f * q * (F - R);
    float sn, cs;
    __sincosf(th, &sn, &cs);
    ell_push(i, j, -an * cs,  an * sn);
    ell_push(j, i, -an * cs, -an * sn);
}

// ---------------- K matrices (R15-proven) ----------------
__global__ void cmat_kernel(const float* __restrict__ W, const float* __restrict__ Wc) {
    __shared__ float wc[40 * 257];
    int mat = blockIdx.y;     // 0..5
    int strip = blockIdx.x;   // 0..7
    int tid = threadIdx.x;
    int part = (mat & 1) ? 0 : 1;
    float s0 = 0.f, s1 = 0.f, s2 = 0.f;
    switch (mat >> 1) {
        case 0: s0 = 1.f; s2 = -1.f; break;
        case 1: s1 = 1.f; break;
        default: s2 = 2.f; break;
    }
    for (int idx = tid; idx < 40 * 256; idx += 256) {
        int c = idx >> 8, f = idx & 255;
        wc[c * 257 + f] = Wc[c * 512 + part * 256 + f];
    }
    __syncthreads();
    int a = strip * 32 + (tid >> 3);
    int cg = tid & 7;
    float acc[5] = {0.f, 0.f, 0.f, 0.f, 0.f};
    for (int f = 0; f < 256; f++) {
        float w = 0.f;
        if (s0 != 0.f) w += s0 * W[a * 256 + f];
        if (s1 != 0.f) w += s1 * W[65536 + a * 256 + f];
        if (s2 != 0.f) w += s2 * W[131072 + a * 256 + f];
        #pragma unroll
        for (int j = 0; j < 5; j++)
            acc[j] = fmaf(w, wc[(cg * 5 + j) * 257 + f], acc[j]);
    }
    #pragma unroll
    for (int j = 0; j < 5; j++)
        g_K[mat][a * 64 + cg * 5 + j] = acc[j];
    for (int idx = tid; idx < 32 * 24; idx += 256) {
        int r = idx / 24, c = 40 + idx % 24;
        g_K[mat][(strip * 32 + r) * 64 + c] = 0.f;
    }
}

// ---------------- C matrices (REWRITTEN: smem-tiled) ----------------
// Cp = sum_{(j,k) in terms(p)} Ej @ Kk ; E0 = W10-W12, E1 = W11, E2 = 2*W12
__global__ void cmatC_kernel(const float* __restrict__ W1) {
    const int nterm[5] = {1, 2, 3, 2, 1};
    const int tj[5][3] = {{0,-1,-1},{1,0,-1},{2,1,0},{2,1,-1},{2,-1,-1}};
    const int tk[5][3] = {{0,-1,-1},{0,1,-1},{0,1,2},{1,2,-1},{2,-1,-1}};
    __shared__ float Es[16][65];
    __shared__ float Ks[64][65];
    int m = blockIdx.x;       // 0..9
    int strip = blockIdx.y;   // 0..15
    int p = m >> 1, part = m & 1;
    int tid = threadIdx.x;
    int a0 = strip * 16;
    int ar = tid >> 4;          // 0..15
    int cc = (tid & 15) * 4;    // 0..60
    float acc[4] = {0.f, 0.f, 0.f, 0.f};
    int nt = nterm[p];
    for (int t = 0; t < nt; t++) {
        int j = tj[p][t], k = tk[p][t];
        const float* Kp = g_K[2 * k + part];
        for (int kt = 0; kt < 4; kt++) {
            int k0 = kt * 64;
            // E tile 16x64 (coalesced along k)
            #pragma unroll
            for (int it = 0; it < 4; it++) {
                int idx = tid + it * 256;
                int r = idx >> 6, c = idx & 63;
                int aa = a0 + r;
                float e;
                if (j == 0)      e = W1[aa * 256 + k0 + c] - W1[131072 + aa * 256 + k0 + c];
                else if (j == 1) e = W1[65536 + aa * 256 + k0 + c];
                else             e = 2.f * W1[131072 + aa * 256 + k0 + c];
                Es[r][c] = e;
            }
            // K tile 64x64 (coalesced)
            #pragma unroll
            for (int it = 0; it < 16; it++) {
                int idx = tid + it * 256;
                int r = idx >> 6, c = idx & 63;
                Ks[r][c] = Kp[(k0 + r) * 64 + c];
            }
            __syncthreads();
            #pragma unroll 8
            for (int kk = 0; kk < 64; kk++) {
                float e = Es[ar][kk];
                acc[0] = fmaf(e, Ks[kk][cc],     acc[0]);
                acc[1] = fmaf(e, Ks[kk][cc + 1], acc[1]);
                acc[2] = fmaf(e, Ks[kk][cc + 2], acc[2]);
                acc[3] = fmaf(e, Ks[kk][cc + 3], acc[3]);
            }
            __syncthreads();
        }
    }
    int a = a0 + ar;
    #pragma unroll
    for (int x = 0; x < 4; x++)
        g_Cm[m][a * 64 + cc + x] = acc[x];
}

// ---------------- bias vectors (R15-proven) ----------------
__global__ void cvec_kernel(const float* __restrict__ b2, const float* __restrict__ Wc) {
    int c = threadIdx.x;
    if (c >= 64) return;
    float s = 0.f;
    if (c < 40)
        for (int f = 0; f < 256; f++)
            s += b2[f] * (Wc[c * 512 + f] + Wc[c * 512 + 256 + f]);
    g_cvec[c] = s;
}

__global__ void uw_kernel(const float* __restrict__ b1) {
    int j = threadIdx.x;
    if (j >= 64) return;
    float ur[3], ui[3];
    #pragma unroll
    for (int k = 0; k < 3; k++) {
        float sre = 0.f, sim = 0.f;
        for (int f = 0; f < 256; f++) {
            float b = b1[f];
            sre = fmaf(b, g_K[2 * k][f * 64 + j], sre);
            sim = fmaf(b, g_K[2 * k + 1][f * 64 + j], sim);
        }
        ur[k] = sre; ui[k] = sim;
    }
    g_w0re[j] = ur[0] - ui[0];
    g_w1re[j] = ur[1] - ui[1];  g_w1im[j] = ur[1] + ui[1];
    g_w2re[j] = ur[2] - ui[2];  g_w2im[j] = ur[2] + ui[2];
}

// ---------------- l vectors (R15-proven) ----------------
__global__ void lvec1_kernel() {
    int warp = threadIdx.x >> 5, lane = threadIdx.x & 31;
    int row = blockIdx.x * 8 + warp;
    int cnt = g_cnt[row];
    if (cnt > ELLW) cnt = ELLW;
    float sre = 0.f, sim = 0.f;
    for (int k = lane; k < cnt; k += 32) {
        int4 v = g_ell[row * ELLW + k];
        sre += __int_as_float(v.y);
        sim += __int_as_float(v.z);
    }
    #pragma unroll
    for (int o = 16; o > 0; o >>= 1) {
        sre += __shfl_xor_sync(0xffffffffu, sre, o);
        sim += __shfl_xor_sync(0xffffffffu, sim, o);
    }
    if (lane == 0) { g_l1re[row] = sre; g_l1im[row] = sim; }
}

__global__ void lvec2_kernel() {
    int warp = threadIdx.x >> 5, lane = threadIdx.x & 31;
    int row = blockIdx.x * 8 + warp;
    int cnt = g_cnt[row];
    if (cnt > ELLW) cnt = ELLW;
    float sre = 0.f, sim = 0.f;
    for (int k = lane; k < cnt; k += 32) {
        int4 v = g_ell[row * ELLW + k];
        float lr = __int_as_float(v.y);
        float li = __int_as_float(v.z);
        float xr = g_l1re[v.x], xi = g_l1im[v.x];
        sre += lr * xr - li * xi;
        sim += lr * xi + li * xr;
    }
    #pragma unroll
    for (int o = 16; o > 0; o >>= 1) {
        sre += __shfl_xor_sync(0xffffffffu, sre, o);
        sim += __shfl_xor_sync(0xffffffffu, sim, o);
    }
    if (lane == 0) { g_l2re[row] = sre; g_l2im[row] = sim; }
}

// ---------------- GEMM machinery (proven) ----------------
__device__ __forceinline__ unsigned pack_bf2(float x, float y) {
    __nv_bfloat162 t;
    t.x = __float2bfloat16_rn(x);
    t.y = __float2bfloat16_rn(y);
    return *reinterpret_cast<unsigned*>(&t);
}

#define MMA_BF16(d, a, b)                                                        \
    asm volatile("mma.sync.aligned.m16n8k16.row.col.f32.bf16.bf16.f32 "          \
                 "{%0,%1,%2,%3},{%4,%5,%6,%7},{%8,%9},{%0,%1,%2,%3};"            \
                 : "+f"(d[0]), "+f"(d[1]), "+f"(d[2]), "+f"(d[3])                 \
                 : "r"(a[0]), "r"(a[1]), "r"(a[2]), "r"(a[3]), "r"(b[0]), "r"(b[1]))

#define LDSM_X4(r, addr)                                                         \
    asm volatile("ldmatrix.sync.aligned.m8n8.x4.shared.b16 {%0,%1,%2,%3}, [%4];" \
                 : "=r"(r[0]), "=r"(r[1]), "=r"(r[2]), "=r"(r[3]) : "r"(addr) : "memory")

#define LDSM_X4_T(r, addr)                                                             \
    asm volatile("ldmatrix.sync.aligned.m8n8.x4.trans.shared.b16 {%0,%1,%2,%3}, [%4];" \
                 : "=r"(r[0]), "=r"(r[1]), "=r"(r[2]), "=r"(r[3]) : "r"(addr) : "memory")

#define AST 20
#define WST 36

// ---------- dual plane products with sign on 2nd term (R15-proven) ----------
struct PPArgs {
    const float* Xr;
    const float* Xi;
    const float* C0[10];
    const float* C1[10];
    float sg[10];
    float* O[10];
};

__global__ void __launch_bounds__(256, 2)
ppY_kernel(PPArgs pp) {
    __shared__ unsigned ash[128 * AST], asl[128 * AST];
    __shared__ unsigned wsh[32 * WST],  wsl[32 * WST];

    int tid = threadIdx.x;
    int lane = tid & 31;
    int warp = tid >> 5;
    int wm = warp >> 2;
    int wn = warp & 3;
    int p = blockIdx.x;
    int m0 = blockIdx.y * 128;
    float* Op = pp.O[p];
    float sg = pp.sg[p];

    float acc[4][2][4];
    #pragma unroll
    for (int mt = 0; mt < 4; mt++)
        #pragma unroll
        for (int nt = 0; nt < 2; nt++)
            #pragma unroll
            for (int r = 0; r < 4; r++) acc[mt][nt][r] = 0.f;

    unsigned a_hi_base = (unsigned)__cvta_generic_to_shared(ash);
    unsigned a_lo_base = (unsigned)__cvta_generic_to_shared(asl);
    unsigned w_hi_base = (unsigned)__cvta_generic_to_shared(wsh);
    unsigned w_lo_base = (unsigned)__cvta_generic_to_shared(wsl);

    unsigned a_off = ((wm * 64 + (lane & 15)) * (AST * 2) + (lane >> 4) * 8) * 2;
    unsigned w_off = (((((lane >> 3) & 1) * 8 + (lane & 7)) * (WST * 2)) + wn * 16 + (lane >> 4) * 8) * 2;

    for (int ks = 0; ks < 16; ks++) {
        int plane = ks >> 3;
        int kc = (ks & 7) * 32;
        const float* Ap = plane ? pp.Xi : pp.Xr;
        const float* Cm = plane ? pp.C1[p] : pp.C0[p];
        float s = plane ? sg : 1.f;
        #pragma unroll
        for (int t = 0; t < 4; t++) {
            int idx = tid + t * 256;
            int r = idx >> 3;
            int c4 = (idx & 7) * 4;
            float4 v = *reinterpret_cast<const float4*>(&Ap[(m0 + r) * 256 + kc + c4]);
            float hx = __bfloat162float(__float2bfloat16_rn(v.x));
            float hy = __bfloat162float(__float2bfloat16_rn(v.y));
            float hz = __bfloat162float(__float2bfloat16_rn(v.z));
            float hw = __bfloat162float(__float2bfloat16_rn(v.w));
            int o = r * AST + (c4 >> 1);
            ash[o]     = pack_bf2(v.x, v.y);
            ash[o + 1] = pack_bf2(v.z, v.w);
            asl[o]     = pack_bf2(v.x - hx, v.y - hy);
            asl[o + 1] = pack_bf2(v.z - hz, v.w - hw);
        }
        #pragma unroll
        for (int t = 0; t < 2; t++) {
            int idx = tid + t * 256;
            int kk = idx >> 4;
            int n4 = (idx & 15) * 4;
            float4 v = *reinterpret_cast<const float4*>(&Cm[(kc + kk) * 64 + n4]);
            v.x *= s; v.y *= s; v.z *= s; v.w *= s;
            float hx = __bfloat162float(__float2bfloat16_rn(v.x));
            float hy = __bfloat162float(__float2bfloat16_rn(v.y));
            float hz = __bfloat162float(__float2bfloat16_rn(v.z));
            float hw = __bfloat162float(__float2bfloat16_rn(v.w));
            int o = kk * WST + (n4 >> 1);
            wsh[o]     = pack_bf2(v.x, v.y);
            wsh[o + 1] = pack_bf2(v.z, v.w);
            wsl[o]     = pack_bf2(v.x - hx, v.y - hy);
            wsl[o + 1] = pack_bf2(v.z - hz, v.w - hw);
        }
        __syncthreads();

        #pragma unroll
        for (int h = 0; h < 32; h += 16) {
            unsigned ah[4][4], al[4][4];
            #pragma unroll
            for (int mt = 0; mt < 4; mt++) {
                unsigned off = a_off + (mt * 16 * AST * 2 + h) * 2;
                LDSM_X4(ah[mt], a_hi_base + off);
                LDSM_X4(al[mt], a_lo_base + off);
            }
            unsigned bh4[4], bl4[4];
            {
                unsigned off = w_off + (h * WST * 2) * 2;
                LDSM_X4_T(bh4, w_hi_base + off);
                LDSM_X4_T(bl4, w_lo_base + off);
            }
            #pragma unroll
            for (int mt = 0; mt < 4; mt++) {
                #pragma unroll
                for (int nt = 0; nt < 2; nt++) {
                    unsigned bh[2] = {bh4[nt * 2], bh4[nt * 2 + 1]};
                    unsigned bl[2] = {bl4[nt * 2], bl4[nt * 2 + 1]};
                    MMA_BF16(acc[mt][nt], ah[mt], bh);
                    MMA_BF16(acc[mt][nt], ah[mt], bl);
                    MMA_BF16(acc[mt][nt], al[mt], bh);
                }
            }
        }
        __syncthreads();
    }

    int g = lane >> 2, tig = lane & 3;
    #pragma unroll
    for (int mt = 0; mt < 4; mt++) {
        #pragma unroll
        for (int nt = 0; nt < 2; nt++) {
            int n = wn * 16 + nt * 8 + tig * 2;
            int ml0 = m0 + wm * 64 + mt * 16 + g;
            float* c0 = acc[mt][nt];
            *reinterpret_cast<float2*>(&Op[ml0 * 64 + n])       = make_float2(c0[0], c0[1]);
            *reinterpret_cast<float2*>(&Op[(ml0 + 8) * 64 + n]) = make_float2(c0[2], c0[3]);
        }
    }
}

// ---------------- Horner narrow spmm (R15-proven) ----------------
__global__ void hornerC_kernel(const float* __restrict__ Yre, const float* __restrict__ Yim,
                               const float* __restrict__ Tinre, const float* __restrict__ Tinim,
                               float* __restrict__ Tore, float* __restrict__ Toim) {
    int row = blockIdx.x;
    int t = threadIdx.x;   // 64
    int cnt = g_cnt[row];
    if (cnt > ELLW) cnt = ELLW;
    __shared__ int   sc[ELLW];
    __shared__ float slr[ELLW];
    __shared__ float sli[ELLW];
    for (int k = t; k < cnt; k += 64) {
        int4 v = g_ell[row * ELLW + k];
        sc [k] = v.x;
        slr[k] = __int_as_float(v.y);
        sli[k] = __int_as_float(v.z);
    }
    __syncthreads();
    float vr = 0.f, vi = 0.f;
    #pragma unroll 4
    for (int k = 0; k < cnt; k++) {
        int c = sc[k];
        float lr = slr[k];
        float li = sli[k];
        float tr = __ldg(&Tinre[c * 64 + t]);
        float ti = __ldg(&Tinim[c * 64 + t]);
        vr = fmaf(lr, tr, vr); vr = fmaf(-li, ti, vr);
        vi = fmaf(lr, ti, vi); vi = fmaf(li, tr, vi);
    }
    int o = row * 64 + t;
    Tore[o] = Yre[o] + vr;
    Toim[o] = Yim[o] + vi;
}

__global__ void hornerI_kernel(const float* __restrict__ Y0im,
                               const float* __restrict__ Tinre, const float* __restrict__ Tinim,
                               float* __restrict__ PIm) {
    int row = blockIdx.x;
    int t = threadIdx.x;   // 64
    int cnt = g_cnt[row];
    if (cnt > ELLW) cnt = ELLW;
    __shared__ int   sc[ELLW];
    __shared__ float slr[ELLW];
    __shared__ float sli[ELLW];
    for (int k = t; k < cnt; k += 64) {
        int4 v = g_ell[row * ELLW + k];
        sc [k] = v.x;
        slr[k] = __int_as_float(v.y);
        sli[k] = __int_as_float(v.z);
    }
    __syncthreads();
    float vi = 0.f;
    #pragma unroll 4
    for (int k = 0; k < cnt; k++) {
        int c = sc[k];
        vi = fmaf(slr[k], __ldg(&Tinim[c * 64 + t]), vi);
        vi = fmaf(sli[k], __ldg(&Tinre[c * 64 + t]), vi);
    }
    int o = row * 64 + t;
    PIm[o] = Y0im[o] + vi;
}

// ---------------- final (R15-proven) ----------------
__global__ void final_kernel(const float* __restrict__ bc, float* __restrict__ out) {
    int warp = threadIdx.x >> 5, lane = threadIdx.x & 31;
    int row = blockIdx.x * 8 + warp;
    float l1r = g_l1re[row], l1i = g_l1im[row];
    float l2r = g_l2re[row], l2i = g_l2im[row];
    float a = -3.4e38f, b = -3.4e38f;
    if (lane < 40) {
        int o = row * 64 + lane;
        a = -g_PIm[o] + g_w0re[lane]
          + l1r * g_w1re[lane] - l1i * g_w1im[lane]
          + l2r * g_w2re[lane] - l2i * g_w2im[lane]
          + g_cvec[lane] + bc[lane];
    }
    if (lane + 32 < 40) {
        int o = row * 64 + lane + 32;
        b = -g_PIm[o] + g_w0re[lane + 32]
          + l1r * g_w1re[lane + 32] - l1i * g_w1im[lane + 32]
          + l2r * g_w2re[lane + 32] - l2i * g_w2im[lane + 32]
          + g_cvec[lane + 32] + bc[lane + 32];
    }
    float m = fmaxf(a, b);
    #pragma unroll
    for (int o = 16; o > 0; o >>= 1) m = fmaxf(m, __shfl_xor_sync(0xffffffffu, m, o));
    float s = ((lane < 40) ? expf(a - m) : 0.f) + ((lane + 32 < 40) ? expf(b - m) : 0.f);
    #pragma unroll
    for (int o = 16; o > 0; o >>= 1) s += __shfl_xor_sync(0xffffffffu, s, o);
    float lse = m + logf(s);
    if (lane < 40)      out[row * 40 + lane]      = a - lse;
    if (lane + 32 < 40) out[row * 40 + lane + 32] = b - lse;
}

// ---------------- launch ----------------
extern "C" void kernel_launch(void* const* d_in, const int* in_sizes, int n_in,
                              void* d_out, int out_size) {
    const float* real = (const float*)d_in[0];
    const float* imag = (const float*)d_in[1];
    const int*   edges = (const int*)d_in[2];
    const float* qp = (const float*)d_in[3];
    const float* ew = (const float*)d_in[4];
    const float* W1 = (const float*)d_in[5];
    const float* b1 = (const float*)d_in[6];
    const float* W2 = (const float*)d_in[7];
    const float* b2 = (const float*)d_in[8];
    const float* Wc = (const float*)d_in[9];
    const float* bc = (const float*)d_in[10];
    float* out = (float*)d_out;
    int E = in_sizes[4];

    float *Cbase, *Ybase, *TAre, *TAim, *TBre, *TBim, *PIm;
    cudaGetSymbolAddress((void**)&Cbase, g_Cm);
    cudaGetSymbolAddress((void**)&Ybase, g_Y);
    cudaGetSymbolAddress((void**)&TAre, g_TAre);
    cudaGetSymbolAddress((void**)&TAim, g_TAim);
    cudaGetSymbolAddress((void**)&TBre, g_TBre);
    cudaGetSymbolAddress((void**)&TBim, g_TBim);
    cudaGetSymbolAddress((void**)&PIm,  g_PIm);

    // graph build
    zero_kernel<<<TSIZE / 256, 256>>>();
    insert_kernel<<<(E + 255) / 256, 256>>>(edges, ew, E);
    dinv_kernel<<<NN / 256, 256>>>();
    emit_kernel<<<TSIZE / 256, 256>>>(qp);

    // weight-side constants
    cmat_kernel<<<dim3(8, 6), 256>>>(W2, Wc);
    cvec_kernel<<<1, 64>>>(b2, Wc);
    cmatC_kernel<<<dim3(10, 16), 256>>>(W1);
    uw_kernel<<<1, 64>>>(b1);
    lvec1_kernel<<<NN / 8, 256>>>();
    lvec2_kernel<<<NN / 8, 256>>>();

    // Y_p = Xc @ C_p  (complex), 10 real outputs
    PPArgs pp;
    pp.Xr = real;
    pp.Xi = imag;
    for (int p = 0; p < 5; p++) {
        pp.C0[2 * p]     = Cbase + (2 * p) * 16384;       // Cp_re
        pp.C1[2 * p]     = Cbase + (2 * p + 1) * 16384;   // Cp_im
        pp.sg[2 * p]     = -1.f;                          // Yre = Xr Cre - Xi Cim
        pp.O [2 * p]     = Ybase + (2 * p) * (NN * 64);
        pp.C0[2 * p + 1] = Cbase + (2 * p + 1) * 16384;
        pp.C1[2 * p + 1] = Cbase + (2 * p) * 16384;
        pp.sg[2 * p + 1] = 1.f;                           // Yim = Xr Cim + Xi Cre
        pp.O [2 * p + 1] = Ybase + (2 * p + 1) * (NN * 64);
    }
    ppY_kernel<<<dim3(10, 32), 256>>>(pp);

    // Horner: P = Y0 + L(Y1 + L(Y2 + L(Y3 + L Y4)))
    #define YRE(p) (Ybase + (2 * (p)) * (NN * 64))
    #define YIM(p) (Ybase + (2 * (p) + 1) * (NN * 64))
    hornerC_kernel<<<NN, 64>>>(YRE(3), YIM(3), YRE(4), YIM(4), TAre, TAim);
    hornerC_kernel<<<NN, 64>>>(YRE(2), YIM(2), TAre, TAim, TBre, TBim);
    hornerC_kernel<<<NN, 64>>>(YRE(1), YIM(1), TBre, TBim, TAre, TAim);
    hornerI_kernel<<<NN, 64>>>(YIM(0), TAre, TAim, PIm);
    #undef YRE
    #undef YIM

    final_kernel<<<NN / 8, 256>>>(bc, out);
}

// round 17
// speedup vs baseline: 1.9750x; 1.2898x over previous
#include <cuda_runtime.h>
#include <cuda_bf16.h>
#include <math.h>

#define NN   4096
#define FF   256
#define ELLW 256
#define TBITS 19
#define TSIZE (1 << TBITS)
#define TMASK (TSIZE - 1)

// ---------------- scratch (device globals) ----------------
__device__ int   g_hkey[TSIZE];
__device__ float g_hvalF[TSIZE];
__device__ float g_hvalR[TSIZE];
__device__ float g_deg[NN];
__device__ float g_dinv[NN];
__device__ int   g_cnt[NN];
__device__ int4  g_ell[NN * ELLW];   // AoS: {col, lre_bits, lim_bits, pad}

// weight-side constants
__device__ float g_WcT[2][256 * 64];  // [part][f][j]  (padded j>=40 -> 0)
__device__ float g_K[6][256 * 64];    // K0re,K0im,K1re,K1im,K2re,K2im
__device__ float g_Cm[10][256 * 64];  // C0re,C0im,...,C4re,C4im
__device__ float g_cvec[64];
__device__ float g_w0re[64], g_w1re[64], g_w1im[64], g_w2re[64], g_w2im[64];
__device__ float g_l1re[NN], g_l1im[NN], g_l2re[NN], g_l2im[NN];

// activations (all 4096x64)
__device__ float g_Y[10][NN * 64];    // Y0re,Y0im,...,Y4re,Y4im
__device__ float g_TAre[NN * 64], g_TAim[NN * 64];
__device__ float g_TBre[NN * 64], g_TBim[NN * 64];
__device__ float g_PIm[NN * 64];

__device__ __forceinline__ unsigned hash_key(int key) {
    return ((unsigned)key * 2654435761u) >> (32 - TBITS);
}

// ---------------- graph build (proven) ----------------
__global__ void zero_kernel() {
    int idx = blockIdx.x * blockDim.x + threadIdx.x;
    if (idx < TSIZE) { g_hkey[idx] = -1; g_hvalF[idx] = 0.f; g_hvalR[idx] = 0.f; }
    if (idx < NN)    { g_deg[idx] = 0.f; g_cnt[idx] = 0; }
}

__global__ void insert_kernel(const int* __restrict__ edges,
                              const float* __restrict__ w, int E) {
    int e = blockIdx.x * blockDim.x + threadIdx.x;
    if (e >= E) return;
    int r = edges[e];
    int c = edges[E + e];
    float we = w[e];
    atomicAdd(&g_deg[r], 0.5f * we);
    atomicAdd(&g_deg[c], 0.5f * we);
    int lo = min(r, c), hi = max(r, c);
    int key = (lo << 12) | hi;
    unsigned h = hash_key(key) & TMASK;
    while (true) {
        int prev = atomicCAS(&g_hkey[h], -1, key);
        if (prev == -1 || prev == key) {
            if (r <= c) atomicAdd(&g_hvalF[h], we);
            else        atomicAdd(&g_hvalR[h], we);
            break;
        }
        h = (h + 1) & TMASK;
    }
}

__global__ void dinv_kernel() {
    int i = blockIdx.x * blockDim.x + threadIdx.x;
    if (i < NN) {
        float d = g_deg[i];
        if (d == 0.f) d = 1.f;
        g_dinv[i] = rsqrtf(d);
    }
}

__device__ __forceinline__ void ell_push(int r, int c, float lre, float lim) {
    int slot = atomicAdd(&g_cnt[r], 1);
    if (slot < ELLW) {
        g_ell[r * ELLW + slot] =
            make_int4(c, __float_as_int(lre), __float_as_int(lim), 0);
    }
}

__global__ void emit_kernel(const float* __restrict__ qp) {
    int s = blockIdx.x * blockDim.x + threadIdx.x;
    if (s >= TSIZE) return;
    int key = g_hkey[s];
    if (key < 0) return;
    int i = key >> 12;
    int j = key & 4095;
    float F = g_hvalF[s];
    float R = g_hvalR[s];
    float q = __ldg(qp);
    if (i == j) {
        float di = g_dinv[i];
        ell_push(i, i, -di * di * F, 0.f);
        return;
    }
    float asym = 0.5f * (F + R);
    float an = g_dinv[i] * asym * g_dinv[j];
    float th = 6.283185307179586f * q * (F - R);
    float sn, cs;
    __sincosf(th, &sn, &cs);
    ell_push(i, j, -an * cs,  an * sn);
    ell_push(j, i, -an * cs, -an * sn);
}

// ---------------- WcT: [part][f][j] = Wc[j*512 + part*256 + f], zero-padded ----------------
__global__ void wct_kernel(const float* __restrict__ Wc) {
    int idx = blockIdx.x * blockDim.x + threadIdx.x;   // 2*256*64
    if (idx >= 2 * 256 * 64) return;
    int part = idx >> 14;
    int f = (idx >> 6) & 255;
    int j = idx & 63;
    g_WcT[part][f * 64 + j] = (j < 40) ? Wc[j * 512 + part * 256 + f] : 0.f;
}

// ---------------- K matrices (parallel smem-tiled): K[m] = Wcombo(W2) @ WcT[part] ----------------
// m: 0 K0re(part1; 1,0,-1) 1 K0im(part0) 2 K1re(0,1,0) 3 K1im 4 K2re(0,0,2) 5 K2im
__global__ void cmatK_kernel(const float* __restrict__ W) {
    __shared__ float Es[8][65];
    __shared__ float Bs[64][65];
    int m = blockIdx.x;       // 0..5
    int strip = blockIdx.y;   // 0..31
    int part = (m & 1) ? 0 : 1;
    float s0 = 0.f, s1 = 0.f, s2 = 0.f;
    switch (m >> 1) {
        case 0: s0 = 1.f; s2 = -1.f; break;
        case 1: s1 = 1.f; break;
        default: s2 = 2.f; break;
    }
    int tid = threadIdx.x;
    int a0 = strip * 8;
    int ar = tid >> 5;          // 0..7
    int cc = (tid & 31) * 2;    // 0..62
    float acc0 = 0.f, acc1 = 0.f;
    for (int kt = 0; kt < 4; kt++) {
        int k0 = kt * 64;
        {   // E tile 8x64
            int idx = tid;      // 0..255 -> 4 rows? 8*64=512: two per thread
            #pragma unroll
            for (int it = 0; it < 2; it++) {
                int r = (idx + it * 256) >> 6, c = (idx + it * 256) & 63;
                int aa = a0 + r;
                float e = 0.f;
                if (s0 != 0.f) e += s0 * W[aa * 256 + k0 + c];
                if (s1 != 0.f) e += s1 * W[65536 + aa * 256 + k0 + c];
                if (s2 != 0.f) e += s2 * W[131072 + aa * 256 + k0 + c];
                Es[r][c] = e;
            }
        }
        #pragma unroll
        for (int it = 0; it < 16; it++) {
            int idx = tid + it * 256;
            int r = idx >> 6, c = idx & 63;
            Bs[r][c] = g_WcT[part][(k0 + r) * 64 + c];
        }
        __syncthreads();
        #pragma unroll 8
        for (int kk = 0; kk < 64; kk++) {
            float e = Es[ar][kk];
            acc0 = fmaf(e, Bs[kk][cc],     acc0);
            acc1 = fmaf(e, Bs[kk][cc + 1], acc1);
        }
        __syncthreads();
    }
    g_K[m][(a0 + ar) * 64 + cc]     = acc0;
    g_K[m][(a0 + ar) * 64 + cc + 1] = acc1;
}

// ---------------- C matrices (parallel smem-tiled): Cp = sum Ej @ Kk ----------------
// E0 = W10 - W12, E1 = W11, E2 = 2*W12
__global__ void cmatC_kernel(const float* __restrict__ W1) {
    const int nterm[5] = {1, 2, 3, 2, 1};
    const int tj[5][3] = {{0,-1,-1},{1,0,-1},{2,1,0},{2,1,-1},{2,-1,-1}};
    const int tk[5][3] = {{0,-1,-1},{0,1,-1},{0,1,2},{1,2,-1},{2,-1,-1}};
    __shared__ float Es[8][65];
    __shared__ float Bs[64][65];
    int m = blockIdx.x;       // 0..9
    int strip = blockIdx.y;   // 0..31
    int p = m >> 1, part = m & 1;
    int tid = threadIdx.x;
    int a0 = strip * 8;
    int ar = tid >> 5;
    int cc = (tid & 31) * 2;
    float acc0 = 0.f, acc1 = 0.f;
    int nt = nterm[p];
    for (int t = 0; t < nt; t++) {
        int j = tj[p][t], k = tk[p][t];
        const float* Kp = g_K[2 * k + part];
        for (int kt = 0; kt < 4; kt++) {
            int k0 = kt * 64;
            #pragma unroll
            for (int it = 0; it < 2; it++) {
                int idx = tid + it * 256;
                int r = idx >> 6, c = idx & 63;
                int aa = a0 + r;
                float e;
                if (j == 0)      e = W1[aa * 256 + k0 + c] - W1[131072 + aa * 256 + k0 + c];
                else if (j == 1) e = W1[65536 + aa * 256 + k0 + c];
                else             e = 2.f * W1[131072 + aa * 256 + k0 + c];
                Es[r][c] = e;
            }
            #pragma unroll
            for (int it = 0; it < 16; it++) {
                int idx = tid + it * 256;
                int r = idx >> 6, c = idx & 63;
                Bs[r][c] = Kp[(k0 + r) * 64 + c];
            }
            __syncthreads();
            #pragma unroll 8
            for (int kk = 0; kk < 64; kk++) {
                float e = Es[ar][kk];
                acc0 = fmaf(e, Bs[kk][cc],     acc0);
                acc1 = fmaf(e, Bs[kk][cc + 1], acc1);
            }
            __syncthreads();
        }
    }
    g_Cm[m][(a0 + ar) * 64 + cc]     = acc0;
    g_Cm[m][(a0 + ar) * 64 + cc + 1] = acc1;
}

// ---------------- bias vectors (parallelized) ----------------
__global__ void cvec_kernel(const float* __restrict__ b2, const float* __restrict__ Wc) {
    __shared__ float red[256];
    int c = blockIdx.x;       // 0..63
    int t = threadIdx.x;
    if (c >= 40) {
        if (t == 0) g_cvec[c] = 0.f;
        return;
    }
    float s = b2[t] * (Wc[c * 512 + t] + Wc[c * 512 + 256 + t]);
    red[t] = s;
    __syncthreads();
    for (int o = 128; o > 0; o >>= 1) {
        if (t < o) red[t] += red[t + o];
        __syncthreads();
    }
    if (t == 0) g_cvec[c] = red[0];
}

__global__ void uw_kernel(const float* __restrict__ b1) {
    __shared__ float red[6][256];
    int j = blockIdx.x;       // 0..63
    int t = threadIdx.x;      // 256 = f
    float b = b1[t];
    #pragma unroll
    for (int m = 0; m < 6; m++)
        red[m][t] = b * g_K[m][t * 64 + j];
    __syncthreads();
    for (int o = 128; o > 0; o >>= 1) {
        if (t < o)
            #pragma unroll
            for (int m = 0; m < 6; m++)
                red[m][t] += red[m][t + o];
        __syncthreads();
    }
    if (t == 0) {
        float ur0 = red[0][0], ui0 = red[1][0];
        float ur1 = red[2][0], ui1 = red[3][0];
        float ur2 = red[4][0], ui2 = red[5][0];
        g_w0re[j] = ur0 - ui0;
        g_w1re[j] = ur1 - ui1;  g_w1im[j] = ur1 + ui1;
        g_w2re[j] = ur2 - ui2;  g_w2im[j] = ur2 + ui2;
    }
}

// ---------------- l vectors (proven) ----------------
__global__ void lvec1_kernel() {
    int warp = threadIdx.x >> 5, lane = threadIdx.x & 31;
    int row = blockIdx.x * 8 + warp;
    int cnt = g_cnt[row];
    if (cnt > ELLW) cnt = ELLW;
    float sre = 0.f, sim = 0.f;
    for (int k = lane; k < cnt; k += 32) {
        int4 v = g_ell[row * ELLW + k];
        sre += __int_as_float(v.y);
        sim += __int_as_float(v.z);
    }
    #pragma unroll
    for (int o = 16; o > 0; o >>= 1) {
        sre += __shfl_xor_sync(0xffffffffu, sre, o);
        sim += __shfl_xor_sync(0xffffffffu, sim, o);
    }
    if (lane == 0) { g_l1re[row] = sre; g_l1im[row] = sim; }
}

__global__ void lvec2_kernel() {
    int warp = threadIdx.x >> 5, lane = threadIdx.x & 31;
    int row = blockIdx.x * 8 + warp;
    int cnt = g_cnt[row];
    if (cnt > ELLW) cnt = ELLW;
    float sre = 0.f, sim = 0.f;
    for (int k = lane; k < cnt; k += 32) {
        int4 v = g_ell[row * ELLW + k];
        float lr = __int_as_float(v.y);
        float li = __int_as_float(v.z);
        float xr = g_l1re[v.x], xi = g_l1im[v.x];
        sre += lr * xr - li * xi;
        sim += lr * xi + li * xr;
    }
    #pragma unroll
    for (int o = 16; o > 0; o >>= 1) {
        sre += __shfl_xor_sync(0xffffffffu, sre, o);
        sim += __shfl_xor_sync(0xffffffffu, sim, o);
    }
    if (lane == 0) { g_l2re[row] = sre; g_l2im[row] = sim; }
}

// ---------------- GEMM machinery (proven) ----------------
__device__ __forceinline__ unsigned pack_bf2(float x, float y) {
    __nv_bfloat162 t;
    t.x = __float2bfloat16_rn(x);
    t.y = __float2bfloat16_rn(y);
    return *reinterpret_cast<unsigned*>(&t);
}

#define MMA_BF16(d, a, b)                                                        \
    asm volatile("mma.sync.aligned.m16n8k16.row.col.f32.bf16.bf16.f32 "          \
                 "{%0,%1,%2,%3},{%4,%5,%6,%7},{%8,%9},{%0,%1,%2,%3};"            \
                 : "+f"(d[0]), "+f"(d[1]), "+f"(d[2]), "+f"(d[3])                 \
                 : "r"(a[0]), "r"(a[1]), "r"(a[2]), "r"(a[3]), "r"(b[0]), "r"(b[1]))

#define LDSM_X4(r, addr)                                                         \
    asm volatile("ldmatrix.sync.aligned.m8n8.x4.shared.b16 {%0,%1,%2,%3}, [%4];" \
                 : "=r"(r[0]), "=r"(r[1]), "=r"(r[2]), "=r"(r[3]) : "r"(addr) : "memory")

#define LDSM_X4_T(r, addr)                                                             \
    asm volatile("ldmatrix.sync.aligned.m8n8.x4.trans.shared.b16 {%0,%1,%2,%3}, [%4];" \
                 : "=r"(r[0]), "=r"(r[1]), "=r"(r[2]), "=r"(r[3]) : "r"(addr) : "memory")

#define AST 20
#define WST 36

// ---------- dual plane products with sign on 2nd term (proven) ----------
struct PPArgs {
    const float* Xr;
    const float* Xi;
    const float* C0[10];
    const float* C1[10];
    float sg[10];
    float* O[10];
};

__global__ void __launch_bounds__(256, 2)
ppY_kernel(PPArgs pp) {
    __shared__ unsigned ash[128 * AST], asl[128 * AST];
    __shared__ unsigned wsh[32 * WST],  wsl[32 * WST];

    int tid = threadIdx.x;
    int lane = tid & 31;
    int warp = tid >> 5;
    int wm = warp >> 2;
    int wn = warp & 3;
    int p = blockIdx.x;
    int m0 = blockIdx.y * 128;
    float* Op = pp.O[p];
    float sg = pp.sg[p];

    float acc[4][2][4];
    #pragma unroll
    for (int mt = 0; mt < 4; mt++)
        #pragma unroll
        for (int nt = 0; nt < 2; nt++)
            #pragma unroll
            for (int r = 0; r < 4; r++) acc[mt][nt][r] = 0.f;

    unsigned a_hi_base = (unsigned)__cvta_generic_to_shared(ash);
    unsigned a_lo_base = (unsigned)__cvta_generic_to_shared(asl);
    unsigned w_hi_base = (unsigned)__cvta_generic_to_shared(wsh);
    unsigned w_lo_base = (unsigned)__cvta_generic_to_shared(wsl);

    unsigned a_off = ((wm * 64 + (lane & 15)) * (AST * 2) + (lane >> 4) * 8) * 2;
    unsigned w_off = (((((lane >> 3) & 1) * 8 + (lane & 7)) * (WST * 2)) + wn * 16 + (lane >> 4) * 8) * 2;

    for (int ks = 0; ks < 16; ks++) {
        int plane = ks >> 3;
        int kc = (ks & 7) * 32;
        const float* Ap = plane ? pp.Xi : pp.Xr;
        const float* Cm = plane ? pp.C1[p] : pp.C0[p];
        float s = plane ? sg : 1.f;
        #pragma unroll
        for (int t = 0; t < 4; t++) {
            int idx = tid + t * 256;
            int r = idx >> 3;
            int c4 = (idx & 7) * 4;
            float4 v = *reinterpret_cast<const float4*>(&Ap[(m0 + r) * 256 + kc + c4]);
            float hx = __bfloat162float(__float2bfloat16_rn(v.x));
            float hy = __bfloat162float(__float2bfloat16_rn(v.y));
            float hz = __bfloat162float(__float2bfloat16_rn(v.z));
            float hw = __bfloat162float(__float2bfloat16_rn(v.w));
            int o = r * AST + (c4 >> 1);
            ash[o]     = pack_bf2(v.x, v.y);
            ash[o + 1] = pack_bf2(v.z, v.w);
            asl[o]     = pack_bf2(v.x - hx, v.y - hy);
            asl[o + 1] = pack_bf2(v.z - hz, v.w - hw);
        }
        #pragma unroll
        for (int t = 0; t < 2; t++) {
            int idx = tid + t * 256;
            int kk = idx >> 4;
            int n4 = (idx & 15) * 4;
            float4 v = *reinterpret_cast<const float4*>(&Cm[(kc + kk) * 64 + n4]);
            v.x *= s; v.y *= s; v.z *= s; v.w *= s;
            float hx = __bfloat162float(__float2bfloat16_rn(v.x));
            float hy = __bfloat162float(__float2bfloat16_rn(v.y));
            float hz = __bfloat162float(__float2bfloat16_rn(v.z));
            float hw = __bfloat162float(__float2bfloat16_rn(v.w));
            int o = kk * WST + (n4 >> 1);
            wsh[o]     = pack_bf2(v.x, v.y);
            wsh[o + 1] = pack_bf2(v.z, v.w);
            wsl[o]     = pack_bf2(v.x - hx, v.y - hy);
            wsl[o + 1] = pack_bf2(v.z - hz, v.w - hw);
        }
        __syncthreads();

        #pragma unroll
        for (int h = 0; h < 32; h += 16) {
            unsigned ah[4][4], al[4][4];
            #pragma unroll
            for (int mt = 0; mt < 4; mt++) {
                unsigned off = a_off + (mt * 16 * AST * 2 + h) * 2;
                LDSM_X4(ah[mt], a_hi_base + off);
                LDSM_X4(al[mt], a_lo_base + off);
            }
            unsigned bh4[4], bl4[4];
            {
                unsigned off = w_off + (h * WST * 2) * 2;
                LDSM_X4_T(bh4, w_hi_base + off);
                LDSM_X4_T(bl4, w_lo_base + off);
            }
            #pragma unroll
            for (int mt = 0; mt < 4; mt++) {
                #pragma unroll
                for (int nt = 0; nt < 2; nt++) {
                    unsigned bh[2] = {bh4[nt * 2], bh4[nt * 2 + 1]};
                    unsigned bl[2] = {bl4[nt * 2], bl4[nt * 2 + 1]};
                    MMA_BF16(acc[mt][nt], ah[mt], bh);
                    MMA_BF16(acc[mt][nt], ah[mt], bl);
                    MMA_BF16(acc[mt][nt], al[mt], bh);
                }
            }
        }
        __syncthreads();
    }

    int g = lane >> 2, tig = lane & 3;
    #pragma unroll
    for (int mt = 0; mt < 4; mt++) {
        #pragma unroll
        for (int nt = 0; nt < 2; nt++) {
            int n = wn * 16 + nt * 8 + tig * 2;
            int ml0 = m0 + wm * 64 + mt * 16 + g;
            float* c0 = acc[mt][nt];
            *reinterpret_cast<float2*>(&Op[ml0 * 64 + n])       = make_float2(c0[0], c0[1]);
            *reinterpret_cast<float2*>(&Op[(ml0 + 8) * 64 + n]) = make_float2(c0[2], c0[3]);
        }
    }
}

// ---------------- Horner narrow spmm (proven) ----------------
__global__ void hornerC_kernel(const float* __restrict__ Yre, const float* __restrict__ Yim,
                               const float* __restrict__ Tinre, const float* __restrict__ Tinim,
                               float* __restrict__ Tore, float* __restrict__ Toim) {
    int row = blockIdx.x;
    int t = threadIdx.x;   // 64
    int cnt = g_cnt[row];
    if (cnt > ELLW) cnt = ELLW;
    __shared__ int   sc[ELLW];
    __shared__ float slr[ELLW];
    __shared__ float sli[ELLW];
    for (int k = t; k < cnt; k += 64) {
        int4 v = g_ell[row * ELLW + k];
        sc [k] = v.x;
        slr[k] = __int_as_float(v.y);
        sli[k] = __int_as_float(v.z);
    }
    __syncthreads();
    float vr = 0.f, vi = 0.f;
    #pragma unroll 4
    for (int k = 0; k < cnt; k++) {
        int c = sc[k];
        float lr = slr[k];
        float li = sli[k];
        float tr = __ldg(&Tinre[c * 64 + t]);
        float ti = __ldg(&Tinim[c * 64 + t]);
        vr = fmaf(lr, tr, vr); vr = fmaf(-li, ti, vr);
        vi = fmaf(lr, ti, vi); vi = fmaf(li, tr, vi);
    }
    int o = row * 64 + t;
    Tore[o] = Yre[o] + vr;
    Toim[o] = Yim[o] + vi;
}

__global__ void hornerI_kernel(const float* __restrict__ Y0im,
                               const float* __restrict__ Tinre, const float* __restrict__ Tinim,
                               float* __restrict__ PIm) {
    int row = blockIdx.x;
    int t = threadIdx.x;   // 64
    int cnt = g_cnt[row];
    if (cnt > ELLW) cnt = ELLW;
    __shared__ int   sc[ELLW];
    __shared__ float slr[ELLW];
    __shared__ float sli[ELLW];
    for (int k = t; k < cnt; k += 64) {
        int4 v = g_ell[row * ELLW + k];
        sc [k] = v.x;
        slr[k] = __int_as_float(v.y);
        sli[k] = __int_as_float(v.z);
    }
    __syncthreads();
    float vi = 0.f;
    #pragma unroll 4
    for (int k = 0; k < cnt; k++) {
        int c = sc[k];
        vi = fmaf(slr[k], __ldg(&Tinim[c * 64 + t]), vi);
        vi = fmaf(sli[k], __ldg(&Tinre[c * 64 + t]), vi);
    }
    int o = row * 64 + t;
    PIm[o] = Y0im[o] + vi;
}

// ---------------- final (proven) ----------------
__global__ void final_kernel(const float* __restrict__ bc, float* __restrict__ out) {
    int warp = threadIdx.x >> 5, lane = threadIdx.x & 31;
    int row = blockIdx.x * 8 + warp;
    float l1r = g_l1re[row], l1i = g_l1im[row];
    float l2r = g_l2re[row], l2i = g_l2im[row];
    float a = -3.4e38f, b = -3.4e38f;
    if (lane < 40) {
        int o = row * 64 + lane;
        a = -g_PIm[o] + g_w0re[lane]
          + l1r * g_w1re[lane] - l1i * g_w1im[lane]
          + l2r * g_w2re[lane] - l2i * g_w2im[lane]
          + g_cvec[lane] + bc[lane];
    }
    if (lane + 32 < 40) {
        int o = row * 64 + lane + 32;
        b = -g_PIm[o] + g_w0re[lane + 32]
          + l1r * g_w1re[lane + 32] - l1i * g_w1im[lane + 32]
          + l2r * g_w2re[lane + 32] - l2i * g_w2im[lane + 32]
          + g_cvec[lane + 32] + bc[lane + 32];
    }
    float m = fmaxf(a, b);
    #pragma unroll
    for (int o = 16; o > 0; o >>= 1) m = fmaxf(m, __shfl_xor_sync(0xffffffffu, m, o));
    float s = ((lane < 40) ? expf(a - m) : 0.f) + ((lane + 32 < 40) ? expf(b - m) : 0.f);
    #pragma unroll
    for (int o = 16; o > 0; o >>= 1) s += __shfl_xor_sync(0xffffffffu, s, o);
    float lse = m + logf(s);
    if (lane < 40)      out[row * 40 + lane]      = a - lse;
    if (lane + 32 < 40) out[row * 40 + lane + 32] = b - lse;
}

// ---------------- launch ----------------
extern "C" void kernel_launch(void* const* d_in, const int* in_sizes, int n_in,
                              void* d_out, int out_size) {
    const float* real = (const float*)d_in[0];
    const float* imag = (const float*)d_in[1];
    const int*   edges = (const int*)d_in[2];
    const float* qp = (const float*)d_in[3];
    const float* ew = (const float*)d_in[4];
    const float* W1 = (const float*)d_in[5];
    const float* b1 = (const float*)d_in[6];
    const float* W2 = (const float*)d_in[7];
    const float* b2 = (const float*)d_in[8];
    const float* Wc = (const float*)d_in[9];
    const float* bc = (const float*)d_in[10];
    float* out = (float*)d_out;
    int E = in_sizes[4];

    float *Cbase, *Ybase, *TAre, *TAim, *TBre, *TBim, *PIm;
    cudaGetSymbolAddress((void**)&Cbase, g_Cm);
    cudaGetSymbolAddress((void**)&Ybase, g_Y);
    cudaGetSymbolAddress((void**)&TAre, g_TAre);
    cudaGetSymbolAddress((void**)&TAim, g_TAim);
    cudaGetSymbolAddress((void**)&TBre, g_TBre);
    cudaGetSymbolAddress((void**)&TBim, g_TBim);
    cudaGetSymbolAddress((void**)&PIm,  g_PIm);

    // graph build
    zero_kernel<<<TSIZE / 256, 256>>>();
    insert_kernel<<<(E + 255) / 256, 256>>>(edges, ew, E);
    dinv_kernel<<<NN / 256, 256>>>();
    emit_kernel<<<TSIZE / 256, 256>>>(qp);

    // weight-side constants (all parallel now)
    wct_kernel<<<(2 * 256 * 64) / 256, 256>>>(Wc);
    cmatK_kernel<<<dim3(6, 32), 256>>>(W2);
    cvec_kernel<<<64, 256>>>(b2, Wc);
    cmatC_kernel<<<dim3(10, 32), 256>>>(W1);
    uw_kernel<<<64, 256>>>(b1);
    lvec1_kernel<<<NN / 8, 256>>>();
    lvec2_kernel<<<NN / 8, 256>>>();

    // Y_p = Xc @ C_p  (complex), 10 real outputs
    PPArgs pp;
    pp.Xr = real;
    pp.Xi = imag;
    for (int p = 0; p < 5; p++) {
        pp.C0[2 * p]     = Cbase + (2 * p) * 16384;
        pp.C1[2 * p]     = Cbase + (2 * p + 1) * 16384;
        pp.sg[2 * p]     = -1.f;
        pp.O [2 * p]     = Ybase + (2 * p) * (NN * 64);
        pp.C0[2 * p + 1] = Cbase + (2 * p + 1) * 16384;
        pp.C1[2 * p + 1] = Cbase + (2 * p) * 16384;
        pp.sg[2 * p + 1] = 1.f;
        pp.O [2 * p + 1] = Ybase + (2 * p + 1) * (NN * 64);
    }
    ppY_kernel<<<dim3(10, 32), 256>>>(pp);

    // Horner: P = Y0 + L(Y1 + L(Y2 + L(Y3 + L Y4)))
    #define YRE(p) (Ybase + (2 * (p)) * (NN * 64))
    #define YIM(p) (Ybase + (2 * (p) + 1) * (NN * 64))
    hornerC_kernel<<<NN, 64>>>(YRE(3), YIM(3), YRE(4), YIM(4), TAre, TAim);
    hornerC_kernel<<<NN, 64>>>(YRE(2), YIM(2), TAre, TAim, TBre, TBim);
    hornerC_kernel<<<NN, 64>>>(YRE(1), YIM(1), TBre, TBim, TAre, TAim);
    hornerI_kernel<<<NN, 64>>>(YIM(0), TAre, TAim, PIm);
    #undef YRE
    #undef YIM

    final_kernel<<<NN / 8, 256>>>(bc, out);
}